// round 15
// baseline (speedup 1.0000x reference)
#include <cuda_runtime.h>
#include <cuda_bf16.h>
#include <cstdint>

// ---------------- problem shape ----------------
static constexpr int B_ROWS = 16384;
static constexpr int C_ROWS = 4096;
static constexpr int KDIM   = 1024;

// ---------------- GEMM tiling (bf16) ----------------
static constexpr int BM = 128;
static constexpr int BN = 128;
static constexpr int BK = 64;                 // bf16 elems per K-chunk
static constexpr int STAGES = 3;
static constexpr int KTILES = KDIM / BK;      // 16
static constexpr int KSTEPS = BK / 16;        // 4 mma k-steps per chunk

// padded smem rows: 64 + 8 halves -> 144B stride (conflict-free ldmatrix)
static constexpr int ROW_H   = BK + 8;        // 72 halves
static constexpr int ROWB    = ROW_H * 2;     // 144 bytes
static constexpr int TILE_B  = 128 * ROWB;    // 18432 bytes per (A or B) stage
static constexpr int OFF_TILES = 128;         // mbarriers live below
static constexpr int OFF_B0  = STAGES * TILE_B;
static constexpr int SMEM_BYTES = OFF_TILES + 2 * STAGES * TILE_B;  // 110720

// ---------------- device scratch (no cudaMalloc allowed) ----------------
__device__ __nv_bfloat16 g_featb[(size_t)B_ROWS * KDIM];
__device__ __nv_bfloat16 g_centb[(size_t)C_ROWS * KDIM];
__device__ float g_x2[B_ROWS];
__device__ float g_c2[C_ROWS];

// ---------------- PTX helpers ----------------
__device__ __forceinline__ uint32_t smem_u32(const void* p) {
    uint32_t a;
    asm("{ .reg .u64 t; cvta.to.shared.u64 t, %1; cvt.u32.u64 %0, t; }"
        : "=r"(a) : "l"(p));
    return a;
}

__device__ __forceinline__ void cp_async16(uint32_t s_addr, const void* g_addr) {
    asm volatile("cp.async.cg.shared.global [%0], [%1], 16;"
                 :: "r"(s_addr), "l"(g_addr) : "memory");
}

#define MBARRIER_INIT(addr, count) \
    asm volatile("mbarrier.init.shared.b64 [%0], %1;" :: "r"((uint32_t)(addr)), "r"((uint32_t)(count)) : "memory")

#define MBARRIER_ARRIVE(addr) \
    asm volatile("mbarrier.arrive.shared.b64 _, [%0];" :: "r"((uint32_t)(addr)) : "memory")

// Deferred arrive when this thread's prior cp.asyncs complete (.noinc: the
// completion counts against the init count; default variant hangs — round 8).
#define CP_MBAR_ARRIVE_NOINC(addr) \
    asm volatile("cp.async.mbarrier.arrive.noinc.shared.b64 [%0];" :: "r"((uint32_t)(addr)) : "memory")

#define MBARRIER_WAIT_PARITY(addr, parity) do {                                   \
    uint32_t _mbar = (uint32_t)(addr);                                            \
    uint32_t _par  = (uint32_t)(parity);                                          \
    uint32_t _done;                                                               \
    asm volatile("{\n\t.reg .pred p;\n\t"                                         \
        "mbarrier.try_wait.parity.acquire.cta.shared::cta.b64 p, [%1], %2;\n\t"   \
        "selp.b32 %0, 1, 0, p;\n\t}"                                              \
        : "=r"(_done) : "r"(_mbar), "r"(_par) : "memory");                        \
    if (!_done) {                                                                 \
        asm volatile("{\n\t.reg .pred P1;\n\t"                                    \
            "WAIT_LOOP_%=:\n\t"                                                   \
            "mbarrier.try_wait.parity.acquire.cta.shared::cta.b64 P1, [%0], %1, 0x989680;\n\t" \
            "@P1 bra.uni WAIT_DONE_%=;\n\t"                                       \
            "bra.uni WAIT_LOOP_%=;\n\t"                                           \
            "WAIT_DONE_%=:\n\t}"                                                  \
            :: "r"(_mbar), "r"(_par) : "memory");                                 \
    }                                                                             \
} while (0)

__device__ __forceinline__ void ldsm_x4(uint32_t& r0, uint32_t& r1, uint32_t& r2, uint32_t& r3,
                                        uint32_t addr) {
    asm volatile("ldmatrix.sync.aligned.m8n8.x4.shared.b16 {%0,%1,%2,%3}, [%4];"
                 : "=r"(r0), "=r"(r1), "=r"(r2), "=r"(r3) : "r"(addr));
}

__device__ __forceinline__ void mma16816(float* d, uint32_t a0, uint32_t a1, uint32_t a2,
                                         uint32_t a3, uint32_t b0, uint32_t b1) {
    asm volatile(
        "mma.sync.aligned.m16n8k16.row.col.f32.bf16.bf16.f32 "
        "{%0,%1,%2,%3}, {%4,%5,%6,%7}, {%8,%9}, {%0,%1,%2,%3};"
        : "+f"(d[0]), "+f"(d[1]), "+f"(d[2]), "+f"(d[3])
        : "r"(a0), "r"(a1), "r"(a2), "r"(a3), "r"(b0), "r"(b1));
}

// ---------------- prep: fp32 -> bf16 + row sum-of-squares, 2 rows/block ----------------
__global__ __launch_bounds__(256)
void prep_kernel(const float* __restrict__ feat, const float* __restrict__ cent) {
    const int t = threadIdx.x;
    const int r0g = blockIdx.x * 2;
    const int r1g = r0g + 1;

    const float* in0; __nv_bfloat16* o0; float* q0; int r0;
    if (r0g < B_ROWS) { r0 = r0g; in0 = feat; o0 = g_featb; q0 = g_x2; }
    else              { r0 = r0g - B_ROWS; in0 = cent; o0 = g_centb; q0 = g_c2; }
    const float* in1; __nv_bfloat16* o1; float* q1; int r1;
    if (r1g < B_ROWS) { r1 = r1g; in1 = feat; o1 = g_featb; q1 = g_x2; }
    else              { r1 = r1g - B_ROWS; in1 = cent; o1 = g_centb; q1 = g_c2; }

    float4 v0 = reinterpret_cast<const float4*>(in0)[(size_t)r0 * 256 + t];
    float4 v1 = reinterpret_cast<const float4*>(in1)[(size_t)r1 * 256 + t];

    float s0 = fmaf(v0.x, v0.x, fmaf(v0.y, v0.y, fmaf(v0.z, v0.z, v0.w * v0.w)));
    float s1 = fmaf(v1.x, v1.x, fmaf(v1.y, v1.y, fmaf(v1.z, v1.z, v1.w * v1.w)));
    #pragma unroll
    for (int o = 16; o > 0; o >>= 1) {
        s0 += __shfl_xor_sync(0xFFFFFFFFu, s0, o);
        s1 += __shfl_xor_sync(0xFFFFFFFFu, s1, o);
    }
    __shared__ float ws0[8], ws1[8];
    if ((t & 31) == 0) { ws0[t >> 5] = s0; ws1[t >> 5] = s1; }
    __syncthreads();
    if (t == 0) {
        float x = 0.0f;
        #pragma unroll
        for (int i = 0; i < 8; i++) x += ws0[i];
        q0[r0] = x;
    }
    if (t == 1) {
        float x = 0.0f;
        #pragma unroll
        for (int i = 0; i < 8; i++) x += ws1[i];
        q1[r1] = x;
    }

    union { __nv_bfloat162 h2[2]; uint2 u; } p0, p1;
    p0.h2[0] = __floats2bfloat162_rn(v0.x, v0.y);
    p0.h2[1] = __floats2bfloat162_rn(v0.z, v0.w);
    p1.h2[0] = __floats2bfloat162_rn(v1.x, v1.y);
    p1.h2[1] = __floats2bfloat162_rn(v1.z, v1.w);
    reinterpret_cast<uint2*>(o0)[(size_t)r0 * 256 + t] = p0.u;
    reinterpret_cast<uint2*>(o1)[(size_t)r1 * 256 + t] = p1.u;
}

// ---------------- main bf16 GEMM + fused distance epilogue ----------------
// R9 kernel (325.7us proven) + producer compaction ONLY: empty-wait + load_A
// + load_B + full-arrive all at kk==0 (full[s2] completes a k-step earlier).
// The round-14 early empty-arrive is REVERTED: it raced the producer's
// overwrite against in-flight LDSM reads (rel_err 7.3e-5 -> 2.9e-4 proved
// silent corruption). empty[s] arms at chunk end, as in R9.
__global__ __launch_bounds__(256, 2)
void dist_gemm_kernel(const __nv_bfloat16* __restrict__ Abf,
                      const __nv_bfloat16* __restrict__ Bbf,
                      const float* __restrict__ x2,
                      const float* __restrict__ c2,
                      float* __restrict__ out) {
    extern __shared__ char smem[];
    const uint32_t sb = smem_u32(smem);
    const int tid = threadIdx.x;
    const int wid = tid >> 5;
    const int lane = tid & 31;

    const int nt = blockIdx.x & 31;           // 32 n-tiles (n-fast for L2 reuse)
    const int mt = blockIdx.x >> 5;           // 128 m-tiles
    const int m_base = mt * BM;
    const int n_base = nt * BN;

    // mbarriers: full[s] at sb+8s, empty[s] at sb+24+8s
    const uint32_t mb_full0 = sb;
    const uint32_t mb_empty0 = sb + 24;
    if (tid == 0) {
        #pragma unroll
        for (int s = 0; s < STAGES; s++) {
            MBARRIER_INIT(mb_full0 + 8 * s, 256);
            MBARRIER_INIT(mb_empty0 + 8 * s, 8);
        }
    }
    __syncthreads();

    const uint32_t tb = sb + OFF_TILES;

    // cp.async mapping: 4 x 16B chunks per thread per (A or B) stage
    const int ld_row = tid >> 3;
    const int ld_c16 = (tid & 7) * 16;
    const __nv_bfloat16* gA = Abf + (size_t)(m_base + ld_row) * KDIM + (tid & 7) * 8;
    const __nv_bfloat16* gB = Bbf + (size_t)(n_base + ld_row) * KDIM + (tid & 7) * 8;
    const uint32_t sA0 = tb + ld_row * ROWB + ld_c16;
    const uint32_t sB0 = tb + OFF_B0 + ld_row * ROWB + ld_c16;

    auto load_A = [&](int s, int kt) {
        const uint32_t st = sA0 + s * TILE_B;
        const size_t gk = (size_t)kt * BK;
        #pragma unroll
        for (int i = 0; i < 4; i++)
            cp_async16(st + i * 32 * ROWB, gA + gk + (size_t)i * 32 * KDIM);
    };
    auto load_B = [&](int s, int kt) {
        const uint32_t st = sB0 + s * TILE_B;
        const size_t gk = (size_t)kt * BK;
        #pragma unroll
        for (int i = 0; i < 4; i++)
            cp_async16(st + i * 32 * ROWB, gB + gk + (size_t)i * 32 * KDIM);
    };

    // warp tiling: 2 (M) x 4 (N); each warp 64x32
    const int wm = wid >> 2;
    const int wn = wid & 3;

    float acc[4][4][4];
    #pragma unroll
    for (int i = 0; i < 4; i++)
        #pragma unroll
        for (int j = 0; j < 4; j++)
            #pragma unroll
            for (int f = 0; f < 4; f++) acc[i][j][f] = 0.0f;

    const uint32_t a_addr0 = (uint32_t)((wm * 64 + (lane & 15)) * ROWB + (lane >> 4) * 16);
    const uint32_t b_addr0 = (uint32_t)((wn * 32 + (lane >> 4) * 8 + (lane & 7)) * ROWB
                                        + ((lane >> 3) & 1) * 16);

    // prologue: writes w=0,1 (producer parity 1 -> immediate pass on fresh mbar)
    MBARRIER_WAIT_PARITY(mb_empty0 + 0, 1);
    load_A(0, 0); load_B(0, 0); CP_MBAR_ARRIVE_NOINC(mb_full0 + 0);
    MBARRIER_WAIT_PARITY(mb_empty0 + 8, 1);
    load_A(1, 1); load_B(1, 1); CP_MBAR_ARRIVE_NOINC(mb_full0 + 8);

    #pragma unroll 1
    for (int kt = 0; kt < KTILES; kt++) {
        const int s = kt % STAGES;
        const int ph = (kt / 3) & 1;
        MBARRIER_WAIT_PARITY(mb_full0 + 8 * s, ph);   // per-warp, no convoy

        const uint32_t aA = tb + s * TILE_B + a_addr0;
        const uint32_t aB = tb + OFF_B0 + s * TILE_B + b_addr0;

        const int w = kt + 2;                          // stage-write index
        const int s2 = w % STAGES;
        const int pph = 1 ^ ((w / 3) & 1);             // producer parity for w
        const bool more = (w < KTILES);

        // cold-start frags for k-step 0
        uint32_t bf[4][2];
        uint32_t ac[4], an[4];
        ldsm_x4(bf[0][0], bf[0][1], bf[1][0], bf[1][1], aB);
        ldsm_x4(bf[2][0], bf[2][1], bf[3][0], bf[3][1], aB + 16 * ROWB);
        ldsm_x4(ac[0], ac[1], ac[2], ac[3], aA);

        #pragma unroll
        for (int kk = 0; kk < KSTEPS; kk++) {
            const uint32_t k0b = kk * 32;
            // mtile 0 (prefetch A1)
            ldsm_x4(an[0], an[1], an[2], an[3], aA + 1 * 16 * ROWB + k0b);
            #pragma unroll
            for (int j = 0; j < 4; j++)
                mma16816(acc[0][j], ac[0], ac[1], ac[2], ac[3], bf[j][0], bf[j][1]);
            // mtile 1 (prefetch A2)
            ldsm_x4(ac[0], ac[1], ac[2], ac[3], aA + 2 * 16 * ROWB + k0b);
            #pragma unroll
            for (int j = 0; j < 4; j++)
                mma16816(acc[1][j], an[0], an[1], an[2], an[3], bf[j][0], bf[j][1]);
            // mtile 2 (prefetch A3)
            ldsm_x4(an[0], an[1], an[2], an[3], aA + 3 * 16 * ROWB + k0b);
            #pragma unroll
            for (int j = 0; j < 4; j++)
                mma16816(acc[2][j], ac[0], ac[1], ac[2], ac[3], bf[j][0], bf[j][1]);
            // mtile 3
            #pragma unroll
            for (int j = 0; j < 4; j++)
                mma16816(acc[3][j], an[0], an[1], an[2], an[3], bf[j][0], bf[j][1]);
            // preload next k-step's B + A0 (WAR on bf/ac is issue-ordered, safe)
            if (kk < KSTEPS - 1) {
                const uint32_t k1b = k0b + 32;
                ldsm_x4(bf[0][0], bf[0][1], bf[1][0], bf[1][1], aB + k1b);
                ldsm_x4(bf[2][0], bf[2][1], bf[3][0], bf[3][1], aB + 16 * ROWB + k1b);
                ldsm_x4(ac[0], ac[1], ac[2], ac[3], aA + k1b);
            }
            // compact producer at kk==0: full[s2] completes a k-step earlier
            if (kk == 0 && more) {
                MBARRIER_WAIT_PARITY(mb_empty0 + 8 * s2, pph);
                load_A(s2, w);
                load_B(s2, w);
                CP_MBAR_ARRIVE_NOINC(mb_full0 + 8 * s2);
            }
        }

        // consumer done with stage s — at chunk end (R9 semantics; the early
        // variant raced the producer overwrite against in-flight LDSM reads)
        if (lane == 0) MBARRIER_ARRIVE(mb_empty0 + 8 * s);
    }

    // ---------------- epilogue: dist = x2[m] + c2[n] - 2*acc ----------------
    const int g = lane >> 2;
    const int q = lane & 3;
    #pragma unroll
    for (int i = 0; i < 4; i++) {
        const int r0 = m_base + wm * 64 + i * 16 + g;
        const int r1 = r0 + 8;
        const float x0 = __ldg(&x2[r0]);
        const float x1 = __ldg(&x2[r1]);
        #pragma unroll
        for (int j = 0; j < 4; j++) {
            const int col = n_base + wn * 32 + j * 8 + q * 2;
            const float cA = __ldg(&c2[col]);
            const float cB = __ldg(&c2[col + 1]);
            float2 v0, v1;
            v0.x = fmaf(-2.0f, acc[i][j][0], x0 + cA);
            v0.y = fmaf(-2.0f, acc[i][j][1], x0 + cB);
            v1.x = fmaf(-2.0f, acc[i][j][2], x1 + cA);
            v1.y = fmaf(-2.0f, acc[i][j][3], x1 + cB);
            *reinterpret_cast<float2*>(&out[(size_t)r0 * C_ROWS + col]) = v0;
            *reinterpret_cast<float2*>(&out[(size_t)r1 * C_ROWS + col]) = v1;
        }
    }
}

// ---------------- host launch ----------------
extern "C" void kernel_launch(void* const* d_in, const int* in_sizes, int n_in,
                              void* d_out, int out_size) {
    (void)in_sizes; (void)n_in; (void)out_size;
    const float* feat = (const float*)d_in[0];
    const float* cent = (const float*)d_in[1];
    float* out = (float*)d_out;

    void *p_fb = nullptr, *p_cb = nullptr, *p_x2 = nullptr, *p_c2 = nullptr;
    cudaGetSymbolAddress(&p_fb, g_featb);
    cudaGetSymbolAddress(&p_cb, g_centb);
    cudaGetSymbolAddress(&p_x2, g_x2);
    cudaGetSymbolAddress(&p_c2, g_c2);

    prep_kernel<<<(B_ROWS + C_ROWS) / 2, 256>>>(feat, cent);

    cudaFuncSetAttribute(dist_gemm_kernel,
                         cudaFuncAttributeMaxDynamicSharedMemorySize, SMEM_BYTES);

    int grid = (B_ROWS / BM) * (C_ROWS / BN);   // 4096
    dist_gemm_kernel<<<grid, 256, SMEM_BYTES>>>(
        (const __nv_bfloat16*)p_fb, (const __nv_bfloat16*)p_cb,
        (const float*)p_x2, (const float*)p_c2, out);
}

// round 16
// speedup vs baseline: 1.0210x; 1.0210x over previous
#include <cuda_runtime.h>
#include <cuda_bf16.h>
#include <cstdint>

// ---------------- problem shape ----------------
static constexpr int B_ROWS = 16384;
static constexpr int C_ROWS = 4096;
static constexpr int KDIM   = 1024;

// ---------------- GEMM tiling (bf16) ----------------
static constexpr int BM = 128;
static constexpr int BN = 128;
static constexpr int BK = 64;                 // bf16 elems per K-chunk
static constexpr int STAGES = 3;
static constexpr int KTILES = KDIM / BK;      // 16
static constexpr int KSTEPS = BK / 16;        // 4 mma k-steps per chunk

// padded smem rows: 64 + 8 halves -> 144B stride (conflict-free ldmatrix)
static constexpr int ROW_H   = BK + 8;        // 72 halves
static constexpr int ROWB    = ROW_H * 2;     // 144 bytes
static constexpr int TILE_B  = 128 * ROWB;    // 18432 bytes per (A or B) stage
static constexpr int OFF_TILES = 128;         // mbarriers live below
static constexpr int OFF_B0  = STAGES * TILE_B;
static constexpr int SMEM_BYTES = OFF_TILES + 2 * STAGES * TILE_B;  // 110720

// ---------------- device scratch (no cudaMalloc allowed) ----------------
__device__ __nv_bfloat16 g_featb[(size_t)B_ROWS * KDIM];
__device__ __nv_bfloat16 g_centb[(size_t)C_ROWS * KDIM];
__device__ float g_x2[B_ROWS];
__device__ float g_c2[C_ROWS];

// ---------------- PTX helpers ----------------
__device__ __forceinline__ uint32_t smem_u32(const void* p) {
    uint32_t a;
    asm("{ .reg .u64 t; cvta.to.shared.u64 t, %1; cvt.u32.u64 %0, t; }"
        : "=r"(a) : "l"(p));
    return a;
}

__device__ __forceinline__ void cp_async16(uint32_t s_addr, const void* g_addr) {
    asm volatile("cp.async.cg.shared.global [%0], [%1], 16;"
                 :: "r"(s_addr), "l"(g_addr) : "memory");
}

#define MBARRIER_INIT(addr, count) \
    asm volatile("mbarrier.init.shared.b64 [%0], %1;" :: "r"((uint32_t)(addr)), "r"((uint32_t)(count)) : "memory")

#define MBARRIER_ARRIVE(addr) \
    asm volatile("mbarrier.arrive.shared.b64 _, [%0];" :: "r"((uint32_t)(addr)) : "memory")

// Deferred arrive when this thread's prior cp.asyncs complete (.noinc: the
// completion counts against the init count; default variant hangs — round 8).
#define CP_MBAR_ARRIVE_NOINC(addr) \
    asm volatile("cp.async.mbarrier.arrive.noinc.shared.b64 [%0];" :: "r"((uint32_t)(addr)) : "memory")

#define MBARRIER_WAIT_PARITY(addr, parity) do {                                   \
    uint32_t _mbar = (uint32_t)(addr);                                            \
    uint32_t _par  = (uint32_t)(parity);                                          \
    uint32_t _done;                                                               \
    asm volatile("{\n\t.reg .pred p;\n\t"                                         \
        "mbarrier.try_wait.parity.acquire.cta.shared::cta.b64 p, [%1], %2;\n\t"   \
        "selp.b32 %0, 1, 0, p;\n\t}"                                              \
        : "=r"(_done) : "r"(_mbar), "r"(_par) : "memory");                        \
    if (!_done) {                                                                 \
        asm volatile("{\n\t.reg .pred P1;\n\t"                                    \
            "WAIT_LOOP_%=:\n\t"                                                   \
            "mbarrier.try_wait.parity.acquire.cta.shared::cta.b64 P1, [%0], %1, 0x989680;\n\t" \
            "@P1 bra.uni WAIT_DONE_%=;\n\t"                                       \
            "bra.uni WAIT_LOOP_%=;\n\t"                                           \
            "WAIT_DONE_%=:\n\t}"                                                  \
            :: "r"(_mbar), "r"(_par) : "memory");                                 \
    }                                                                             \
} while (0)

__device__ __forceinline__ void ldsm_x4(uint32_t& r0, uint32_t& r1, uint32_t& r2, uint32_t& r3,
                                        uint32_t addr) {
    asm volatile("ldmatrix.sync.aligned.m8n8.x4.shared.b16 {%0,%1,%2,%3}, [%4];"
                 : "=r"(r0), "=r"(r1), "=r"(r2), "=r"(r3) : "r"(addr));
}

__device__ __forceinline__ void mma16816(float* d, uint32_t a0, uint32_t a1, uint32_t a2,
                                         uint32_t a3, uint32_t b0, uint32_t b1) {
    asm volatile(
        "mma.sync.aligned.m16n8k16.row.col.f32.bf16.bf16.f32 "
        "{%0,%1,%2,%3}, {%4,%5,%6,%7}, {%8,%9}, {%0,%1,%2,%3};"
        : "+f"(d[0]), "+f"(d[1]), "+f"(d[2]), "+f"(d[3])
        : "r"(a0), "r"(a1), "r"(a2), "r"(a3), "r"(b0), "r"(b1));
}

// ---------------- prep: warp-per-row, MLP=8, shuffle-only reduction ----------------
// 8 warps/block, one row per warp. 8 front-batched float4 loads per thread
// (fully coalesced 128B segments), bf16 convert + 8B stores, warp shuffle
// reduction — no smem, no __syncthreads.
__global__ __launch_bounds__(256)
void prep_kernel(const float* __restrict__ feat, const float* __restrict__ cent) {
    const int lane = threadIdx.x & 31;
    const int warp = threadIdx.x >> 5;
    const int rowg = blockIdx.x * 8 + warp;

    const float* in; __nv_bfloat16* o; float* q; int row;
    if (rowg < B_ROWS) { row = rowg; in = feat; o = g_featb; q = g_x2; }
    else               { row = rowg - B_ROWS; in = cent; o = g_centb; q = g_c2; }

    const float4* src = reinterpret_cast<const float4*>(in) + (size_t)row * 256;
    uint2* dst = reinterpret_cast<uint2*>(o) + (size_t)row * 256;

    // front-batch all 8 loads (MLP=8)
    float4 v[8];
    #pragma unroll
    for (int k = 0; k < 8; k++) v[k] = src[k * 32 + lane];

    float s = 0.0f;
    #pragma unroll
    for (int k = 0; k < 8; k++) {
        s = fmaf(v[k].x, v[k].x, s);
        s = fmaf(v[k].y, v[k].y, s);
        s = fmaf(v[k].z, v[k].z, s);
        s = fmaf(v[k].w, v[k].w, s);
        union { __nv_bfloat162 h2[2]; uint2 u; } pk;
        pk.h2[0] = __floats2bfloat162_rn(v[k].x, v[k].y);
        pk.h2[1] = __floats2bfloat162_rn(v[k].z, v[k].w);
        dst[k * 32 + lane] = pk.u;
    }
    #pragma unroll
    for (int off = 16; off > 0; off >>= 1) s += __shfl_xor_sync(0xFFFFFFFFu, s, off);
    if (lane == 0) q[row] = s;
}

// ---------------- main bf16 GEMM + fused distance epilogue ----------------
// R9 kernel verbatim (325.7us proven; GEMM 308us, tensor 74.3%). Six
// structural variants (warp shape, smem traffic, convoy removal, cold-start
// removal, persistent CTAs, producer slack) all plateau at 73-74% tensor —
// this schedule is the validated optimum for legacy mma.sync on sm_103.
__global__ __launch_bounds__(256, 2)
void dist_gemm_kernel(const __nv_bfloat16* __restrict__ Abf,
                      const __nv_bfloat16* __restrict__ Bbf,
                      const float* __restrict__ x2,
                      const float* __restrict__ c2,
                      float* __restrict__ out) {
    extern __shared__ char smem[];
    const uint32_t sb = smem_u32(smem);
    const int tid = threadIdx.x;
    const int wid = tid >> 5;
    const int lane = tid & 31;

    const int nt = blockIdx.x & 31;           // 32 n-tiles (n-fast for L2 reuse)
    const int mt = blockIdx.x >> 5;           // 128 m-tiles
    const int m_base = mt * BM;
    const int n_base = nt * BN;

    // mbarriers: full[s] at sb+8s, empty[s] at sb+24+8s
    const uint32_t mb_full0 = sb;
    const uint32_t mb_empty0 = sb + 24;
    if (tid == 0) {
        #pragma unroll
        for (int s = 0; s < STAGES; s++) {
            MBARRIER_INIT(mb_full0 + 8 * s, 256);
            MBARRIER_INIT(mb_empty0 + 8 * s, 8);
        }
    }
    __syncthreads();

    const uint32_t tb = sb + OFF_TILES;

    // cp.async mapping: 4 x 16B chunks per thread per (A or B) stage
    const int ld_row = tid >> 3;
    const int ld_c16 = (tid & 7) * 16;
    const __nv_bfloat16* gA = Abf + (size_t)(m_base + ld_row) * KDIM + (tid & 7) * 8;
    const __nv_bfloat16* gB = Bbf + (size_t)(n_base + ld_row) * KDIM + (tid & 7) * 8;
    const uint32_t sA0 = tb + ld_row * ROWB + ld_c16;
    const uint32_t sB0 = tb + OFF_B0 + ld_row * ROWB + ld_c16;

    auto load_A = [&](int s, int kt) {
        const uint32_t st = sA0 + s * TILE_B;
        const size_t gk = (size_t)kt * BK;
        #pragma unroll
        for (int i = 0; i < 4; i++)
            cp_async16(st + i * 32 * ROWB, gA + gk + (size_t)i * 32 * KDIM);
    };
    auto load_B = [&](int s, int kt) {
        const uint32_t st = sB0 + s * TILE_B;
        const size_t gk = (size_t)kt * BK;
        #pragma unroll
        for (int i = 0; i < 4; i++)
            cp_async16(st + i * 32 * ROWB, gB + gk + (size_t)i * 32 * KDIM);
    };

    // warp tiling: 2 (M) x 4 (N); each warp 64x32
    const int wm = wid >> 2;
    const int wn = wid & 3;

    float acc[4][4][4];
    #pragma unroll
    for (int i = 0; i < 4; i++)
        #pragma unroll
        for (int j = 0; j < 4; j++)
            #pragma unroll
            for (int f = 0; f < 4; f++) acc[i][j][f] = 0.0f;

    const uint32_t a_addr0 = (uint32_t)((wm * 64 + (lane & 15)) * ROWB + (lane >> 4) * 16);
    const uint32_t b_addr0 = (uint32_t)((wn * 32 + (lane >> 4) * 8 + (lane & 7)) * ROWB
                                        + ((lane >> 3) & 1) * 16);

    // prologue: writes w=0,1 (producer parity 1 -> immediate pass on fresh mbar)
    MBARRIER_WAIT_PARITY(mb_empty0 + 0, 1);
    load_A(0, 0); load_B(0, 0); CP_MBAR_ARRIVE_NOINC(mb_full0 + 0);
    MBARRIER_WAIT_PARITY(mb_empty0 + 8, 1);
    load_A(1, 1); load_B(1, 1); CP_MBAR_ARRIVE_NOINC(mb_full0 + 8);

    #pragma unroll 1
    for (int kt = 0; kt < KTILES; kt++) {
        const int s = kt % STAGES;
        const int ph = (kt / 3) & 1;
        MBARRIER_WAIT_PARITY(mb_full0 + 8 * s, ph);   // per-warp, no convoy

        const uint32_t aA = tb + s * TILE_B + a_addr0;
        const uint32_t aB = tb + OFF_B0 + s * TILE_B + b_addr0;

        const int w = kt + 2;                          // stage-write index
        const int s2 = w % STAGES;
        const int pph = 1 ^ ((w / 3) & 1);             // producer parity for w
        const bool more = (w < KTILES);

        // cold-start frags for k-step 0
        uint32_t bf[4][2];
        uint32_t ac[4], an[4];
        ldsm_x4(bf[0][0], bf[0][1], bf[1][0], bf[1][1], aB);
        ldsm_x4(bf[2][0], bf[2][1], bf[3][0], bf[3][1], aB + 16 * ROWB);
        ldsm_x4(ac[0], ac[1], ac[2], ac[3], aA);

        #pragma unroll
        for (int kk = 0; kk < KSTEPS; kk++) {
            const uint32_t k0b = kk * 32;
            // mtile 0 (prefetch A1)
            ldsm_x4(an[0], an[1], an[2], an[3], aA + 1 * 16 * ROWB + k0b);
            #pragma unroll
            for (int j = 0; j < 4; j++)
                mma16816(acc[0][j], ac[0], ac[1], ac[2], ac[3], bf[j][0], bf[j][1]);
            // mtile 1 (prefetch A2)
            ldsm_x4(ac[0], ac[1], ac[2], ac[3], aA + 2 * 16 * ROWB + k0b);
            #pragma unroll
            for (int j = 0; j < 4; j++)
                mma16816(acc[1][j], an[0], an[1], an[2], an[3], bf[j][0], bf[j][1]);
            // mtile 2 (prefetch A3)
            ldsm_x4(an[0], an[1], an[2], an[3], aA + 3 * 16 * ROWB + k0b);
            #pragma unroll
            for (int j = 0; j < 4; j++)
                mma16816(acc[2][j], ac[0], ac[1], ac[2], ac[3], bf[j][0], bf[j][1]);
            // mtile 3
            #pragma unroll
            for (int j = 0; j < 4; j++)
                mma16816(acc[3][j], an[0], an[1], an[2], an[3], bf[j][0], bf[j][1]);
            // preload next k-step's B + A0 (WAR on bf/ac is issue-ordered, safe)
            if (kk < KSTEPS - 1) {
                const uint32_t k1b = k0b + 32;
                ldsm_x4(bf[0][0], bf[0][1], bf[1][0], bf[1][1], aB + k1b);
                ldsm_x4(bf[2][0], bf[2][1], bf[3][0], bf[3][1], aB + 16 * ROWB + k1b);
                ldsm_x4(ac[0], ac[1], ac[2], ac[3], aA + k1b);
            }
            // producer side, spread across k-steps 0/1 (R9 schedule)
            if (kk == 0 && more) {
                MBARRIER_WAIT_PARITY(mb_empty0 + 8 * s2, pph);
                load_A(s2, w);
            }
            if (kk == 1 && more) {
                load_B(s2, w);
                CP_MBAR_ARRIVE_NOINC(mb_full0 + 8 * s2);
            }
        }

        // consumer done with stage s (chunk end — R9 semantics; the early
        // arrive variant silently corrupted results in round 14)
        if (lane == 0) MBARRIER_ARRIVE(mb_empty0 + 8 * s);
    }

    // ---------------- epilogue: dist = x2[m] + c2[n] - 2*acc ----------------
    const int g = lane >> 2;
    const int q = lane & 3;
    #pragma unroll
    for (int i = 0; i < 4; i++) {
        const int r0 = m_base + wm * 64 + i * 16 + g;
        const int r1 = r0 + 8;
        const float x0 = __ldg(&x2[r0]);
        const float x1 = __ldg(&x2[r1]);
        #pragma unroll
        for (int j = 0; j < 4; j++) {
            const int col = n_base + wn * 32 + j * 8 + q * 2;
            const float cA = __ldg(&c2[col]);
            const float cB = __ldg(&c2[col + 1]);
            float2 v0, v1;
            v0.x = fmaf(-2.0f, acc[i][j][0], x0 + cA);
            v0.y = fmaf(-2.0f, acc[i][j][1], x0 + cB);
            v1.x = fmaf(-2.0f, acc[i][j][2], x1 + cA);
            v1.y = fmaf(-2.0f, acc[i][j][3], x1 + cB);
            *reinterpret_cast<float2*>(&out[(size_t)r0 * C_ROWS + col]) = v0;
            *reinterpret_cast<float2*>(&out[(size_t)r1 * C_ROWS + col]) = v1;
        }
    }
}

// ---------------- host launch ----------------
extern "C" void kernel_launch(void* const* d_in, const int* in_sizes, int n_in,
                              void* d_out, int out_size) {
    (void)in_sizes; (void)n_in; (void)out_size;
    const float* feat = (const float*)d_in[0];
    const float* cent = (const float*)d_in[1];
    float* out = (float*)d_out;

    void *p_fb = nullptr, *p_cb = nullptr, *p_x2 = nullptr, *p_c2 = nullptr;
    cudaGetSymbolAddress(&p_fb, g_featb);
    cudaGetSymbolAddress(&p_cb, g_centb);
    cudaGetSymbolAddress(&p_x2, g_x2);
    cudaGetSymbolAddress(&p_c2, g_c2);

    prep_kernel<<<(B_ROWS + C_ROWS) / 8, 256>>>(feat, cent);

    cudaFuncSetAttribute(dist_gemm_kernel,
                         cudaFuncAttributeMaxDynamicSharedMemorySize, SMEM_BYTES);

    int grid = (B_ROWS / BM) * (C_ROWS / BN);   // 4096
    dist_gemm_kernel<<<grid, 256, SMEM_BYTES>>>(
        (const __nv_bfloat16*)p_fb, (const __nv_bfloat16*)p_cb,
        (const float*)p_x2, (const float*)p_c2, out);
}